// round 11
// baseline (speedup 1.0000x reference)
#include <cuda_runtime.h>
#include <cstdint>

#define B_ 8
#define N_ 2048
#define F_ 64
#define O_ 64
#define ALPHA 0.2f

#define BM  128
#define BKC 16
#define KSPLIT 2
#define KPART (N_ / KSPLIT)       // 1024
#define NCH (KPART / BKC)         // 64 chunks per CTA
#define SA_STRIDE 24              // perm layout: 16 slots + pad
#define SA_BUF (BM * SA_STRIDE)   // 3072 floats per buf; 2 bufs = 24576 B

// Scratch (allocation-free rule: __device__ globals)
__device__ float g_d[B_ * N_];                         // d[b,n] = rsqrt(rowsum+1)
__device__ float g_Y[(size_t)B_ * N_ * O_];            // Y = d*(X@W), fp32 row-major
__device__ float g_Yt[(size_t)B_ * (N_ / 8) * 512];    // 4 MB fragment-major tf32 Y
__device__ float g_Zp[(size_t)KSPLIT * B_ * N_ * O_];  // 8 MB K-split partials

__device__ __forceinline__ float round_tf32(float x) {
    uint32_t h;
    asm("cvt.rna.tf32.f32 %0, %1;" : "=r"(h) : "f"(x));
    return __uint_as_float(h);
}
__device__ __forceinline__ void mma8(float* c, const float* a, const float* b) {
    asm("mma.sync.aligned.m16n8k8.row.col.f32.tf32.tf32.f32 "
        "{%0,%1,%2,%3}, {%4,%5,%6,%7}, {%8,%9}, {%0,%1,%2,%3};"
        : "+f"(c[0]), "+f"(c[1]), "+f"(c[2]), "+f"(c[3])
        : "r"(__float_as_uint(a[0])), "r"(__float_as_uint(a[1])),
          "r"(__float_as_uint(a[2])), "r"(__float_as_uint(a[3])),
          "r"(__float_as_uint(b[0])), "r"(__float_as_uint(b[1])));
}

// ---------------------------------------------------------------------------
// Pass 1: rowsum -> d, Y = d*(X@W) (fp32), plus fragment-major tf32 Yt.
// One block = 8 rows = exactly one k8 block; blockIdx.x == b*256 + k8.
// Yt layout: float idx = (b*256+k8)*512 + wn*256 + lane*8 + (j*4+ni)
//   holding tf32(Y[8*k8 + tig + 4j][wn*32 + ni*8 + g]) with lane = g*4+tig.
// ---------------------------------------------------------------------------
__global__ void __launch_bounds__(256) prep_kernel(const float* __restrict__ A,
                                                   const float* __restrict__ X,
                                                   const float* __restrict__ W) {
    __shared__ float sW[F_ * O_];
    __shared__ float sX[8][F_];
    __shared__ float sYt[576];   // skewed staging: idx = wn*288 + lane2*9 + s
    const int t = threadIdx.x;
    const int warp = t >> 5;     // row-in-block kr (0..7)
    const int lane = t & 31;
    const int row = blockIdx.x * 8 + warp;   // flattened [b][n]

    #pragma unroll
    for (int i = t; i < F_ * O_; i += 256) sW[i] = W[i];
    #pragma unroll
    for (int i = t; i < 8 * F_; i += 256)
        sX[i >> 6][i & 63] = X[(size_t)blockIdx.x * 8 * F_ + i];
    __syncthreads();

    const float4* arow = (const float4*)(A + (size_t)row * N_);
    float s = 0.f;
    #pragma unroll 4
    for (int i = lane; i < N_ / 4; i += 32) {
        float4 v = arow[i];
        s += (v.x + v.y) + (v.z + v.w);
    }
    #pragma unroll
    for (int off = 16; off; off >>= 1) s += __shfl_xor_sync(0xffffffffu, s, off);
    const float dd = rsqrtf(s + 1.0f);
    if (lane == 0) g_d[row] = dd;

    float acc0 = 0.f, acc1 = 0.f;
    #pragma unroll
    for (int f = 0; f < F_; f++) {
        const float xv = sX[warp][f];
        acc0 += xv * sW[f * O_ + lane];
        acc1 += xv * sW[f * O_ + lane + 32];
    }
    const float y0 = dd * acc0, y1 = dd * acc1;
    g_Y[(size_t)row * O_ + lane]      = y0;
    g_Y[(size_t)row * O_ + lane + 32] = y1;

    // Stage rounded values into skewed SMEM (conflict-free: banks g*4+ni+C)
    const int tig = warp & 3, j = warp >> 2;
    {
        const int c0 = lane;            // wn=0
        const int lane2a = (c0 & 7) * 4 + tig;
        sYt[(lane2a * 9) + (j * 4 + ((c0 >> 3) & 3))] = round_tf32(y0);
        const int c1 = lane + 32;       // wn=1
        const int lane2b = (c1 & 7) * 4 + tig;
        sYt[288 + (lane2b * 9) + (j * 4 + ((c1 >> 3) & 3))] = round_tf32(y1);
    }
    __syncthreads();

    // Copy 512 staged floats to contiguous global block (2 per thread)
    {
        const int d0 = 2 * t;
        const int wn = d0 >> 8, lane2 = (d0 >> 3) & 31, sidx = d0 & 7;
        const int src = wn * 288 + lane2 * 9 + sidx;
        *(float2*)(g_Yt + (size_t)blockIdx.x * 512 + d0) =
            make_float2(sYt[src], sYt[src + 1]);
    }
}

// ---------------------------------------------------------------------------
// Pass 2: Z-partial = A[:, kpart] @ Y[kpart, :] single-product tf32 mma.
// BM=128, 8 warps (4 wm x 2 wn), warp tile 32x32. A via perm SMEM (LDS.64
// frags); Y b-frags read directly from L2-resident g_Yt (4 LDG.128/chunk),
// register double-buffered. Fused A copy-out. grid (16,8,2)=256, 2 CTAs/SM.
// ---------------------------------------------------------------------------
__global__ void __launch_bounds__(256, 2) gemm_tc(const float* __restrict__ A,
                                                  float* __restrict__ outA) {
    __shared__ float sAh[2 * SA_BUF];

    const int b = blockIdx.y;
    const int ks = blockIdx.z;
    const int rowBase = blockIdx.x * BM;
    const int kBase = ks * KPART;
    const int k8Base = ks * (KPART / 8);     // 128 k8-blocks per part
    const float* Ab = A + (size_t)b * N_ * N_;
    float* outAb = outA ? outA + (size_t)b * N_ * N_ : nullptr;

    const int t = threadIdx.x;
    const int w = t >> 5;
    const int lane = t & 31;
    const int g = lane >> 2;
    const int tig = lane & 3;
    const int wm = w & 3;         // 32-row block
    const int wn = w >> 2;        // 32-col block

    // A loader: thread t handles rows a_r and a_r+64, float4 at col a_c
    const int a_r = t >> 2;                  // 0..63
    const int a_c = (t & 3) * 4;
    const int a_p0 = ((a_c >> 3) << 3) + ((a_c >> 2) & 1);

    // Y fragment source: per chunk, 2 k8 blocks, 2 LDG.128 each
    const float* ybase = g_Yt + ((size_t)(b * 256 + k8Base) * 512) + wn * 256 + lane * 8;

    float4 cA[2], nA[2];
    float cY[16], nY[16];

    auto ldgA = [&](int i, float4 (&va)[2]) {
        const float* p = Ab + (size_t)(rowBase + a_r) * N_ + kBase + i * BKC + a_c;
        va[0] = *(const float4*)(p);
        va[1] = *(const float4*)(p + 64 * N_);
    };
    auto ldgY = [&](int i, float (&y)[16]) {
        const float* p = ybase + (size_t)(2 * i) * 512;
        *(float4*)(y)      = *(const float4*)(p);
        *(float4*)(y + 4)  = *(const float4*)(p + 4);
        *(float4*)(y + 8)  = *(const float4*)(p + 512);
        *(float4*)(y + 12) = *(const float4*)(p + 516);
    };
    auto stsA = [&](int buf, const float4 (&va)[2]) {
        float* p1 = sAh + buf * SA_BUF + a_r * SA_STRIDE + a_p0;
        p1[0] = round_tf32(va[0].x);
        p1[2] = round_tf32(va[0].y);
        p1[4] = round_tf32(va[0].z);
        p1[6] = round_tf32(va[0].w);
        float* p2 = p1 + 64 * SA_STRIDE;
        p2[0] = round_tf32(va[1].x);
        p2[2] = round_tf32(va[1].y);
        p2[4] = round_tf32(va[1].z);
        p2[6] = round_tf32(va[1].w);
    };
    auto stgA = [&](int i, const float4 (&va)[2]) {
        if (outAb) {
            float* p = outAb + (size_t)(rowBase + a_r) * N_ + kBase + i * BKC + a_c;
            *(float4*)(p) = va[0];
            *(float4*)(p + 64 * N_) = va[1];
        }
    };

    float acc[2][4][4];
    #pragma unroll
    for (int mi = 0; mi < 2; mi++)
        #pragma unroll
        for (int ni = 0; ni < 4; ni++)
            #pragma unroll
            for (int j = 0; j < 4; j++) acc[mi][ni][j] = 0.f;

    ldgA(0, cA);
    ldgY(0, cY);
    stsA(0, cA);
    stgA(0, cA);
    __syncthreads();

    const int a_base = (wm * 32 + g) * SA_STRIDE + 2 * tig;

    for (int i = 0; i < NCH; i++) {
        const int buf = i & 1;
        if (i + 1 < NCH) { ldgA(i + 1, nA); ldgY(i + 1, nY); }

        const float* ah = sAh + buf * SA_BUF + a_base;
        #pragma unroll
        for (int kk = 0; kk < 2; kk++) {
            float fah[2][4];
            #pragma unroll
            for (int mi = 0; mi < 2; mi++) {
                const float2 h0 = *(const float2*)(ah + mi * 16 * SA_STRIDE + kk * 8);
                const float2 h1 = *(const float2*)(ah + mi * 16 * SA_STRIDE + 8 * SA_STRIDE + kk * 8);
                fah[mi][0] = h0.x; fah[mi][1] = h1.x;
                fah[mi][2] = h0.y; fah[mi][3] = h1.y;
            }
            #pragma unroll
            for (int ni = 0; ni < 4; ni++) {
                const float fb[2] = {cY[kk * 8 + ni], cY[kk * 8 + 4 + ni]};
                mma8(acc[0][ni], fah[0], fb);
                mma8(acc[1][ni], fah[1], fb);
            }
        }

        if (i + 1 < NCH) {
            stsA(buf ^ 1, nA);
            stgA(i + 1, nA);
            cA[0] = nA[0]; cA[1] = nA[1];
            #pragma unroll
            for (int j = 0; j < 16; j++) cY[j] = nY[j];
        }
        __syncthreads();
    }

    // ---- store raw partial Z to scratch ----
    float* zp = g_Zp + ((size_t)(ks * B_ + b) * N_) * O_;
    #pragma unroll
    for (int mi = 0; mi < 2; mi++) {
        const int r0 = rowBase + wm * 32 + mi * 16 + g;
        #pragma unroll
        for (int ni = 0; ni < 4; ni++) {
            const int col = wn * 32 + ni * 8 + 2 * tig;
            *(float2*)(zp + (size_t)r0 * O_ + col)       = make_float2(acc[mi][ni][0], acc[mi][ni][1]);
            *(float2*)(zp + (size_t)(r0 + 8) * O_ + col) = make_float2(acc[mi][ni][2], acc[mi][ni][3]);
        }
    }
}

// ---------------------------------------------------------------------------
// Pass 3: combine 2 partials + diagonal + scale + bias + leaky.
// ---------------------------------------------------------------------------
__global__ void __launch_bounds__(256) combine_kernel(const float* __restrict__ bias,
                                                      float* __restrict__ outX) {
    const int t = threadIdx.x;
    const int r = blockIdx.x * 16 + (t >> 4);
    const int c = (t & 15) * 4;
    const size_t off = (size_t)r * O_ + c;
    const size_t part = (size_t)B_ * N_ * O_;
    const float4 z0 = *(const float4*)(g_Zp + off);
    const float4 z1 = *(const float4*)(g_Zp + part + off);
    const float4 yv = *(const float4*)(g_Y + off);
    const float4 bb = *(const float4*)(bias + c);
    const float dd = g_d[r];
    float4 o;
    o.x = dd * ((z0.x + z1.x) + yv.x) + bb.x;
    o.y = dd * ((z0.y + z1.y) + yv.y) + bb.y;
    o.z = dd * ((z0.z + z1.z) + yv.z) + bb.z;
    o.w = dd * ((z0.w + z1.w) + yv.w) + bb.w;
    o.x = fmaxf(o.x, ALPHA * o.x);
    o.y = fmaxf(o.y, ALPHA * o.y);
    o.z = fmaxf(o.z, ALPHA * o.z);
    o.w = fmaxf(o.w, ALPHA * o.w);
    *(float4*)(outX + off) = o;
}

extern "C" void kernel_launch(void* const* d_in, const int* in_sizes, int n_in,
                              void* d_out, int out_size) {
    const float* X    = (const float*)d_in[0];  // [B, N, F]
    const float* A    = (const float*)d_in[1];  // [B, N, N]
    const float* W    = (const float*)d_in[2];  // [F, O]
    const float* bias = (const float*)d_in[3];  // [O]

    const size_t nX = (size_t)B_ * N_ * O_;
    const size_t nA = (size_t)B_ * N_ * N_;
    float* outX = (float*)d_out;
    float* outA = ((size_t)out_size >= nX + nA) ? outX + nX : nullptr;

    prep_kernel<<<B_ * N_ / 8, 256>>>(A, X, W);
    dim3 grid(N_ / BM, B_, KSPLIT);
    gemm_tc<<<grid, 256>>>(A, outA);
    combine_kernel<<<B_ * N_ / 16, 256>>>(bias, outX);
}